// round 10
// baseline (speedup 1.0000x reference)
#include <cuda_runtime.h>

#define DIN    9
#define NPAIR  45
#define NTRI   165

// smem layout (bytes):
//  A: 9 rows x 16B               @ 0    (ch: [e0, e1p0, e1p1, e1p2])
//  B: groups by a (rows b=a..8)  @ 160  packed 40B rows (9 ch + pad), pairs 80B-aligned
//  C: groups by (a,b) (c=b..8)   @ 2000 packed 40B rows (10 ch), pairs 80B-aligned
//  total 8800 B
#define SB_FLOATS 2200

typedef unsigned long long u64;

__device__ __forceinline__ constexpr int grp_bytes(int L) { return (L / 2) * 80 + (L & 1) * 48; }
__device__ __forceinline__ constexpr int b_group_off(int a) {
    int o = 160;
    for (int x = 0; x < a; x++) o += grp_bytes(9 - x);
    return o;
}
__device__ __forceinline__ constexpr int c_group_off(int a, int b) {
    int o = 2000;
    for (int x = 0; x < a; x++)
        for (int y = x; y < 9; y++) o += grp_bytes(9 - y);
    for (int y = a; y < b; y++) o += grp_bytes(9 - y);
    return o;
}

__device__ __forceinline__ u64 pk2(float lo, float hi) {
    u64 r; asm("mov.b64 %0, {%1, %2};" : "=l"(r) : "f"(lo), "f"(hi)); return r;
}
__device__ __forceinline__ void upk2(float& lo, float& hi, u64 v) {
    asm("mov.b64 {%0, %1}, %2;" : "=f"(lo), "=f"(hi) : "l"(v));
}
__device__ __forceinline__ u64 ffma2(u64 a, u64 b, u64 c) {
    u64 d; asm("fma.rn.f32x2 %0, %1, %2, %3;" : "=l"(d) : "l"(a), "l"(b), "l"(c)); return d;
}
__device__ __forceinline__ u64 fmul2(u64 a, u64 b) {
    u64 d; asm("mul.rn.f32x2 %0, %1, %2;" : "=l"(d) : "l"(a), "l"(b)); return d;
}
__device__ __forceinline__ u64 duplo(u64 v) { float lo, hi; upk2(lo, hi, v); return pk2(lo, lo); }
__device__ __forceinline__ u64 duphi(u64 v) { float lo, hi; upk2(lo, hi, v); return pk2(hi, hi); }

// accumulate one 5-u64 row into both items' accumulators
__device__ __forceinline__ void acc5(u64* X0, u64* X1,
                                     u64 v0, u64 v1, u64 v2, u64 v3, u64 v4,
                                     u64 d0, u64 d1)
{
    X0[0] = ffma2(v0, d0, X0[0]);
    X0[1] = ffma2(v1, d0, X0[1]);
    X0[2] = ffma2(v2, d0, X0[2]);
    X0[3] = ffma2(v3, d0, X0[3]);
    X0[4] = ffma2(v4, d0, X0[4]);
    X1[0] = ffma2(v0, d1, X1[0]);
    X1[1] = ffma2(v1, d1, X1[1]);
    X1[2] = ffma2(v2, d1, X1[2]);
    X1[3] = ffma2(v3, d1, X1[3]);
    X1[4] = ffma2(v4, d1, X1[4]);
}

// per-item epilogue: scalar weight contraction + store
__device__ __forceinline__ void epilogue(
    const float* TAs, const float* TBs, const float* TCs,
    const float* __restrict__ W0, const float* __restrict__ W1,
    const float* __restrict__ W2, const float* __restrict__ W3,
    const float* __restrict__ W4, const float* __restrict__ W5,
    int e, int m, float* obase)
{
    float o0 = W0[e * 128 + m] * TAs[0];
    #pragma unroll
    for (int s = 0; s < 3; s++) o0 = fmaf(W2[(e * 3 + s) * 128 + m], TBs[s], o0);
    #pragma unroll
    for (int s = 0; s < 4; s++) o0 = fmaf(W4[(e * 4 + s) * 128 + m], TCs[s], o0);

    float o1[3];
    const float w1 = W1[e * 128 + m];
    #pragma unroll
    for (int p = 0; p < 3; p++) o1[p] = w1 * TAs[1 + p];
    #pragma unroll
    for (int s = 0; s < 2; s++) {
        const float w = W3[(e * 2 + s) * 128 + m];
        #pragma unroll
        for (int p = 0; p < 3; p++) o1[p] = fmaf(w, TBs[3 + s * 3 + p], o1[p]);
    }
    #pragma unroll
    for (int s = 0; s < 2; s++) {
        const float w = W5[(e * 2 + s) * 128 + m];
        #pragma unroll
        for (int p = 0; p < 3; p++) o1[p] = fmaf(w, TCs[4 + s * 3 + p], o1[p]);
    }

    obase[m] = o0;
    #pragma unroll
    for (int p = 0; p < 3; p++) obase[128 + m * 3 + p] = o1[p];
}

// ---------------------------------------------------------------------------
// blockDim = (64, 4): 4 nodes per block, 2 items (m, m+64) per thread.
// Packed 40B rows, 80B row-pair loads: 5 LDS.128 per 2 rows (was 6).
// ---------------------------------------------------------------------------
__global__ void __launch_bounds__(256, 2)
symcon_kernel(const float* __restrict__ feats,   // (N, 1152)
              const int*   __restrict__ species, // (N,)
              const float* __restrict__ b0, const float* __restrict__ b1,
              const float* __restrict__ b2, const float* __restrict__ b3,
              const float* __restrict__ b4, const float* __restrict__ b5,
              const float* __restrict__ W0, const float* __restrict__ W1,
              const float* __restrict__ W2, const float* __restrict__ W3,
              const float* __restrict__ W4, const float* __restrict__ W5,
              float* __restrict__ out)            // (N, 512)
{
    __shared__ float sb[SB_FLOATS];   // 8800 B

    const int tid = threadIdx.y * 64 + threadIdx.x;
    const char* sbc = reinterpret_cast<const char*>(sb);

    const int m0 = threadIdx.x;          // 0..63
    const int m1 = m0 + 64;
    const int n  = blockIdx.x * 4 + threadIdx.y;

    // ---- hoisted global loads (latency hides behind prep) ----
    const int e = species[n];
    const float* fbase = feats + n * 1152;

    u64 f2[9];
    f2[0] = pk2(fbase[m0], fbase[m1]);
    #pragma unroll
    for (int k = 0; k < 3; k++)
        f2[1 + k] = pk2(fbase[128 + m0 * 3 + k], fbase[128 + m1 * 3 + k]);
    #pragma unroll
    for (int k = 0; k < 5; k++)
        f2[4 + k] = pk2(fbase[512 + m0 * 5 + k], fbase[512 + m1 * 5 + k]);

    // ---- fused prep: symmetrize bases into packed smem ----
    if (tid < DIN) {
        float* row = sb + tid * 4;   // 16B rows
        row[0] = b0[tid];
        #pragma unroll
        for (int p = 0; p < 3; p++) row[1 + p] = b1[tid * 3 + p];
    }
    if (tid < NPAIR) {
        int a = 0, rem = tid;
        while (rem >= DIN - a) { rem -= DIN - a; a++; }
        const int b = a + rem;
        const int k = b - a;
        float* row = reinterpret_cast<float*>(
            const_cast<char*>(sbc) + b_group_off(a) + (k / 2) * 80 + (k & 1) * 40);
        #pragma unroll
        for (int s = 0; s < 3; s++) {
            float v = b2[(a * 9 + b) * 3 + s];
            if (a != b) v += b2[(b * 9 + a) * 3 + s];
            row[s] = v;
        }
        #pragma unroll
        for (int s = 0; s < 2; s++)
            #pragma unroll
            for (int p = 0; p < 3; p++) {
                float v = b3[((a * 9 + b) * 2 + s) * 3 + p];
                if (a != b) v += b3[((b * 9 + a) * 2 + s) * 3 + p];
                row[3 + s * 3 + p] = v;
            }
        row[9] = 0.f;   // pad channel
    }
    if (tid < NTRI) {
        // decode triple index -> (a, b, c), a <= b <= c
        int a = 0, rem = tid;
        for (;; a++) {
            const int cnt = (DIN - a) * (DIN - a + 1) / 2;
            if (rem < cnt) break;
            rem -= cnt;
        }
        int b = a;
        for (;; b++) {
            const int cnt = DIN - b;
            if (rem < cnt) break;
            rem -= cnt;
        }
        const int c = b + rem;

        const int pi[6] = {a, a, b, b, c, c};
        const int pj[6] = {b, c, a, c, a, b};
        const int pk[6] = {c, b, c, a, b, a};
        float acc[10];
        #pragma unroll
        for (int q = 0; q < 10; q++) acc[q] = 0.f;
        for (int q = 0; q < 6; q++) {
            bool dup = false;
            for (int r = 0; r < q; r++)
                if (pi[r] == pi[q] && pj[r] == pj[q] && pk[r] == pk[q]) { dup = true; break; }
            if (dup) continue;
            const int base = (pi[q] * 9 + pj[q]) * 9 + pk[q];
            for (int s = 0; s < 4; s++) acc[s] += b4[base * 4 + s];
            for (int s = 0; s < 2; s++)
                for (int p = 0; p < 3; p++)
                    acc[4 + s * 3 + p] += b5[(base * 2 + s) * 3 + p];
        }
        const int k = c - b;
        float* row = reinterpret_cast<float*>(
            const_cast<char*>(sbc) + c_group_off(a, b) + (k / 2) * 80 + (k & 1) * 40);
        #pragma unroll
        for (int q = 0; q < 10; q++) row[q] = acc[q];
    }
    __syncthreads();

    // channel-pair accumulators, separate per item
    u64 A0[2], A1[2], B0[5], B1[5], C0[5], C1[5];
    #pragma unroll
    for (int q = 0; q < 2; q++) { A0[q] = 0ull; A1[q] = 0ull; }
    #pragma unroll
    for (int q = 0; q < 5; q++) { B0[q] = 0ull; B1[q] = 0ull; C0[q] = 0ull; C1[q] = 0ull; }

    // nu=1 (16B rows)
    #pragma unroll
    for (int a = 0; a < 9; a++) {
        const ulonglong2 v = *reinterpret_cast<const ulonglong2*>(sbc + a * 16);
        const u64 d0 = duplo(f2[a]);
        const u64 d1 = duphi(f2[a]);
        A0[0] = ffma2(v.x, d0, A0[0]);
        A0[1] = ffma2(v.y, d0, A0[1]);
        A1[0] = ffma2(v.x, d1, A1[0]);
        A1[1] = ffma2(v.y, d1, A1[1]);
    }

    // nu=2: pairs of rows within each a-group (5 LDS / 2 rows)
    #pragma unroll
    for (int a = 0; a < 9; a++) {
        const int L = 9 - a;
        const char* go = sbc + b_group_off(a);
        #pragma unroll
        for (int k = 0; k + 1 < L; k += 2) {
            const u64 P0 = fmul2(f2[a], f2[a + k]);
            const u64 P1 = fmul2(f2[a], f2[a + k + 1]);
            const u64 d00 = duplo(P0), d01 = duphi(P0);
            const u64 d10 = duplo(P1), d11 = duphi(P1);
            const char* base = go + (k / 2) * 80;
            const ulonglong2 x0 = *reinterpret_cast<const ulonglong2*>(base);
            const ulonglong2 x1 = *reinterpret_cast<const ulonglong2*>(base + 16);
            const ulonglong2 x2 = *reinterpret_cast<const ulonglong2*>(base + 32);
            const ulonglong2 x3 = *reinterpret_cast<const ulonglong2*>(base + 48);
            const ulonglong2 x4 = *reinterpret_cast<const ulonglong2*>(base + 64);
            acc5(B0, B1, x0.x, x0.y, x1.x, x1.y, x2.x, d00, d01);
            acc5(B0, B1, x2.y, x3.x, x3.y, x4.x, x4.y, d10, d11);
        }
        if (L & 1) {
            const int k = L - 1;
            const u64 P = fmul2(f2[a], f2[a + k]);
            const u64 d0 = duplo(P), d1 = duphi(P);
            const char* base = go + (k / 2) * 80;
            const ulonglong2 x0 = *reinterpret_cast<const ulonglong2*>(base);
            const ulonglong2 x1 = *reinterpret_cast<const ulonglong2*>(base + 16);
            const u64 x2 = *reinterpret_cast<const u64*>(base + 32);
            acc5(B0, B1, x0.x, x0.y, x1.x, x1.y, x2, d0, d1);
        }
    }

    // nu=3: pairs of rows within each (a,b) c-group (5 LDS / 2 rows, Pab shared)
    #pragma unroll
    for (int a = 0; a < 9; a++) {
        #pragma unroll
        for (int b = a; b < 9; b++) {
            const u64 Pab = fmul2(f2[a], f2[b]);
            const int L = 9 - b;
            const char* go = sbc + c_group_off(a, b);
            #pragma unroll
            for (int k = 0; k + 1 < L; k += 2) {
                const u64 F0 = fmul2(Pab, f2[b + k]);
                const u64 F1 = fmul2(Pab, f2[b + k + 1]);
                const u64 d00 = duplo(F0), d01 = duphi(F0);
                const u64 d10 = duplo(F1), d11 = duphi(F1);
                const char* base = go + (k / 2) * 80;
                const ulonglong2 x0 = *reinterpret_cast<const ulonglong2*>(base);
                const ulonglong2 x1 = *reinterpret_cast<const ulonglong2*>(base + 16);
                const ulonglong2 x2 = *reinterpret_cast<const ulonglong2*>(base + 32);
                const ulonglong2 x3 = *reinterpret_cast<const ulonglong2*>(base + 48);
                const ulonglong2 x4 = *reinterpret_cast<const ulonglong2*>(base + 64);
                acc5(C0, C1, x0.x, x0.y, x1.x, x1.y, x2.x, d00, d01);
                acc5(C0, C1, x2.y, x3.x, x3.y, x4.x, x4.y, d10, d11);
            }
            if (L & 1) {
                const int k = L - 1;
                const u64 F = fmul2(Pab, f2[b + k]);
                const u64 d0 = duplo(F), d1 = duphi(F);
                const char* base = go + (k / 2) * 80;
                const ulonglong2 x0 = *reinterpret_cast<const ulonglong2*>(base);
                const ulonglong2 x1 = *reinterpret_cast<const ulonglong2*>(base + 16);
                const u64 x2 = *reinterpret_cast<const u64*>(base + 32);
                acc5(C0, C1, x0.x, x0.y, x1.x, x1.y, x2, d0, d1);
            }
        }
    }

    // unpack accumulators and run per-item epilogue
    float* obase = out + n * 512;
    {
        float TAs[4], TBs[10], TCs[10];
        upk2(TAs[0], TAs[1], A0[0]); upk2(TAs[2], TAs[3], A0[1]);
        #pragma unroll
        for (int q = 0; q < 5; q++) upk2(TBs[2 * q], TBs[2 * q + 1], B0[q]);
        #pragma unroll
        for (int q = 0; q < 5; q++) upk2(TCs[2 * q], TCs[2 * q + 1], C0[q]);
        epilogue(TAs, TBs, TCs, W0, W1, W2, W3, W4, W5, e, m0, obase);
    }
    {
        float TAs[4], TBs[10], TCs[10];
        upk2(TAs[0], TAs[1], A1[0]); upk2(TAs[2], TAs[3], A1[1]);
        #pragma unroll
        for (int q = 0; q < 5; q++) upk2(TBs[2 * q], TBs[2 * q + 1], B1[q]);
        #pragma unroll
        for (int q = 0; q < 5; q++) upk2(TCs[2 * q], TCs[2 * q + 1], C1[q]);
        epilogue(TAs, TBs, TCs, W0, W1, W2, W3, W4, W5, e, m1, obase);
    }
}

// ---------------------------------------------------------------------------
extern "C" void kernel_launch(void* const* d_in, const int* in_sizes, int n_in,
                              void* d_out, int out_size)
{
    const float* feats   = (const float*)d_in[0];
    const int*   species = (const int*)  d_in[1];
    const float* b0 = (const float*)d_in[2];
    const float* w0 = (const float*)d_in[3];
    const float* b1 = (const float*)d_in[4];
    const float* w1 = (const float*)d_in[5];
    const float* b2 = (const float*)d_in[6];
    const float* w2 = (const float*)d_in[7];
    const float* b3 = (const float*)d_in[8];
    const float* w3 = (const float*)d_in[9];
    const float* b4 = (const float*)d_in[10];
    const float* w4 = (const float*)d_in[11];
    const float* b5 = (const float*)d_in[12];
    const float* w5 = (const float*)d_in[13];
    float* out = (float*)d_out;

    dim3 block(64, 4);
    dim3 grid(2048 / 4);
    symcon_kernel<<<grid, block>>>(feats, species,
                                   b0, b1, b2, b3, b4, b5,
                                   w0, w1, w2, w3, w4, w5, out);
}

// round 12
// speedup vs baseline: 1.5529x; 1.5529x over previous
#include <cuda_runtime.h>

#define DIN    9
#define NPAIR  45
#define NTRI   165

// smem layout (bytes):
//  A: 9 rows x 16B               @ 0    (ch: [e0, e1p0, e1p1, e1p2])
//  B: groups by a (rows b=a..8)  @ 160  packed 40B rows (9 ch + pad), pairs 80B-aligned
//  C: groups by (a,b) (c=b..8)   @ 2000 packed 40B rows (10 ch), pairs 80B-aligned
//  total 8800 B
#define SB_FLOATS 2200

typedef unsigned long long u64;

// ---- compile-time offset tables (forces immediate LDS addressing) ----
struct OffTbl { int B[9]; int C[45]; };
constexpr int grp_bytes_h(int L) { return (L / 2) * 80 + (L % 2) * 48; }
constexpr OffTbl make_offs() {
    OffTbl t{};
    int o = 160;
    for (int a = 0; a < 9; a++) { t.B[a] = o; o += grp_bytes_h(9 - a); }
    int pr = 0;
    for (int a = 0; a < 9; a++)
        for (int b = a; b < 9; b++) { t.C[pr++] = o; o += grp_bytes_h(9 - b); }
    return t;
}
__device__ constexpr OffTbl OFFS = make_offs();

__device__ __forceinline__ u64 pk2(float lo, float hi) {
    u64 r; asm("mov.b64 %0, {%1, %2};" : "=l"(r) : "f"(lo), "f"(hi)); return r;
}
__device__ __forceinline__ void upk2(float& lo, float& hi, u64 v) {
    asm("mov.b64 {%0, %1}, %2;" : "=f"(lo), "=f"(hi) : "l"(v));
}
__device__ __forceinline__ u64 ffma2(u64 a, u64 b, u64 c) {
    u64 d; asm("fma.rn.f32x2 %0, %1, %2, %3;" : "=l"(d) : "l"(a), "l"(b), "l"(c)); return d;
}
__device__ __forceinline__ u64 fmul2(u64 a, u64 b) {
    u64 d; asm("mul.rn.f32x2 %0, %1, %2;" : "=l"(d) : "l"(a), "l"(b)); return d;
}
__device__ __forceinline__ u64 duplo(u64 v) { float lo, hi; upk2(lo, hi, v); return pk2(lo, lo); }
__device__ __forceinline__ u64 duphi(u64 v) { float lo, hi; upk2(lo, hi, v); return pk2(hi, hi); }

// accumulate one 5-u64 row into both items' accumulators
__device__ __forceinline__ void acc5(u64* X0, u64* X1,
                                     u64 v0, u64 v1, u64 v2, u64 v3, u64 v4,
                                     u64 d0, u64 d1)
{
    X0[0] = ffma2(v0, d0, X0[0]);
    X0[1] = ffma2(v1, d0, X0[1]);
    X0[2] = ffma2(v2, d0, X0[2]);
    X0[3] = ffma2(v3, d0, X0[3]);
    X0[4] = ffma2(v4, d0, X0[4]);
    X1[0] = ffma2(v0, d1, X1[0]);
    X1[1] = ffma2(v1, d1, X1[1]);
    X1[2] = ffma2(v2, d1, X1[2]);
    X1[3] = ffma2(v3, d1, X1[3]);
    X1[4] = ffma2(v4, d1, X1[4]);
}

// per-item epilogue: scalar weight contraction + store
__device__ __forceinline__ void epilogue(
    const float* TAs, const float* TBs, const float* TCs,
    const float* __restrict__ W0, const float* __restrict__ W1,
    const float* __restrict__ W2, const float* __restrict__ W3,
    const float* __restrict__ W4, const float* __restrict__ W5,
    int e, int m, float* obase)
{
    float o0 = W0[e * 128 + m] * TAs[0];
    #pragma unroll
    for (int s = 0; s < 3; s++) o0 = fmaf(W2[(e * 3 + s) * 128 + m], TBs[s], o0);
    #pragma unroll
    for (int s = 0; s < 4; s++) o0 = fmaf(W4[(e * 4 + s) * 128 + m], TCs[s], o0);

    float o1[3];
    const float w1 = W1[e * 128 + m];
    #pragma unroll
    for (int p = 0; p < 3; p++) o1[p] = w1 * TAs[1 + p];
    #pragma unroll
    for (int s = 0; s < 2; s++) {
        const float w = W3[(e * 2 + s) * 128 + m];
        #pragma unroll
        for (int p = 0; p < 3; p++) o1[p] = fmaf(w, TBs[3 + s * 3 + p], o1[p]);
    }
    #pragma unroll
    for (int s = 0; s < 2; s++) {
        const float w = W5[(e * 2 + s) * 128 + m];
        #pragma unroll
        for (int p = 0; p < 3; p++) o1[p] = fmaf(w, TCs[4 + s * 3 + p], o1[p]);
    }

    obase[m] = o0;
    #pragma unroll
    for (int p = 0; p < 3; p++) obase[128 + m * 3 + p] = o1[p];
}

// ---------------------------------------------------------------------------
// blockDim = (64, 4): 4 nodes per block, 2 items (m, m+64) per thread.
// Packed 40B rows, 80B row-pair loads: 5 LDS.128 per 2 rows; all smem
// addresses are base + compile-time immediate (OFFS tables).
// ---------------------------------------------------------------------------
__global__ void __launch_bounds__(256, 2)
symcon_kernel(const float* __restrict__ feats,   // (N, 1152)
              const int*   __restrict__ species, // (N,)
              const float* __restrict__ b0, const float* __restrict__ b1,
              const float* __restrict__ b2, const float* __restrict__ b3,
              const float* __restrict__ b4, const float* __restrict__ b5,
              const float* __restrict__ W0, const float* __restrict__ W1,
              const float* __restrict__ W2, const float* __restrict__ W3,
              const float* __restrict__ W4, const float* __restrict__ W5,
              float* __restrict__ out)            // (N, 512)
{
    __shared__ float sb[SB_FLOATS];   // 8800 B

    const int tid = threadIdx.y * 64 + threadIdx.x;
    const char* sbc = reinterpret_cast<const char*>(sb);

    const int m0 = threadIdx.x;          // 0..63
    const int m1 = m0 + 64;
    const int n  = blockIdx.x * 4 + threadIdx.y;

    // ---- hoisted global loads (latency hides behind prep) ----
    const int e = species[n];
    const float* fbase = feats + n * 1152;

    u64 f2[9];
    f2[0] = pk2(fbase[m0], fbase[m1]);
    #pragma unroll
    for (int k = 0; k < 3; k++)
        f2[1 + k] = pk2(fbase[128 + m0 * 3 + k], fbase[128 + m1 * 3 + k]);
    #pragma unroll
    for (int k = 0; k < 5; k++)
        f2[4 + k] = pk2(fbase[512 + m0 * 5 + k], fbase[512 + m1 * 5 + k]);

    // ---- fused prep: symmetrize bases into packed smem ----
    if (tid < DIN) {
        float* row = sb + tid * 4;   // 16B rows
        row[0] = b0[tid];
        #pragma unroll
        for (int p = 0; p < 3; p++) row[1 + p] = b1[tid * 3 + p];
    }
    if (tid < NPAIR) {
        int a = 0, rem = tid;
        while (rem >= DIN - a) { rem -= DIN - a; a++; }
        const int b = a + rem;
        const int k = b - a;
        float* row = reinterpret_cast<float*>(
            const_cast<char*>(sbc) + OFFS.B[a] + (k / 2) * 80 + (k & 1) * 40);
        #pragma unroll
        for (int s = 0; s < 3; s++) {
            float v = b2[(a * 9 + b) * 3 + s];
            if (a != b) v += b2[(b * 9 + a) * 3 + s];
            row[s] = v;
        }
        #pragma unroll
        for (int s = 0; s < 2; s++)
            #pragma unroll
            for (int p = 0; p < 3; p++) {
                float v = b3[((a * 9 + b) * 2 + s) * 3 + p];
                if (a != b) v += b3[((b * 9 + a) * 2 + s) * 3 + p];
                row[3 + s * 3 + p] = v;
            }
        row[9] = 0.f;   // pad channel
    }
    if (tid < NTRI) {
        // decode triple index -> (a, b, c), a <= b <= c; pr = pair index of (a,b)
        int a = 0, rem = tid;
        for (;; a++) {
            const int cnt = (DIN - a) * (DIN - a + 1) / 2;
            if (rem < cnt) break;
            rem -= cnt;
        }
        int b = a;
        for (;; b++) {
            const int cnt = DIN - b;
            if (rem < cnt) break;
            rem -= cnt;
        }
        const int c = b + rem;
        const int pr = a * 9 - (a * (a - 1)) / 2 + (b - a);

        const int pi[6] = {a, a, b, b, c, c};
        const int pj[6] = {b, c, a, c, a, b};
        const int pk[6] = {c, b, c, a, b, a};
        float acc[10];
        #pragma unroll
        for (int q = 0; q < 10; q++) acc[q] = 0.f;
        for (int q = 0; q < 6; q++) {
            bool dup = false;
            for (int r = 0; r < q; r++)
                if (pi[r] == pi[q] && pj[r] == pj[q] && pk[r] == pk[q]) { dup = true; break; }
            if (dup) continue;
            const int base = (pi[q] * 9 + pj[q]) * 9 + pk[q];
            for (int s = 0; s < 4; s++) acc[s] += b4[base * 4 + s];
            for (int s = 0; s < 2; s++)
                for (int p = 0; p < 3; p++)
                    acc[4 + s * 3 + p] += b5[(base * 2 + s) * 3 + p];
        }
        const int k = c - b;
        float* row = reinterpret_cast<float*>(
            const_cast<char*>(sbc) + OFFS.C[pr] + (k / 2) * 80 + (k & 1) * 40);
        #pragma unroll
        for (int q = 0; q < 10; q++) row[q] = acc[q];
    }
    __syncthreads();

    // channel-pair accumulators, separate per item
    u64 A0[2], A1[2], B0[5], B1[5], C0[5], C1[5];
    #pragma unroll
    for (int q = 0; q < 2; q++) { A0[q] = 0ull; A1[q] = 0ull; }
    #pragma unroll
    for (int q = 0; q < 5; q++) { B0[q] = 0ull; B1[q] = 0ull; C0[q] = 0ull; C1[q] = 0ull; }

    // nu=1 (16B rows)
    #pragma unroll
    for (int a = 0; a < 9; a++) {
        const ulonglong2 v = *reinterpret_cast<const ulonglong2*>(sbc + a * 16);
        const u64 d0 = duplo(f2[a]);
        const u64 d1 = duphi(f2[a]);
        A0[0] = ffma2(v.x, d0, A0[0]);
        A0[1] = ffma2(v.y, d0, A0[1]);
        A1[0] = ffma2(v.x, d1, A1[0]);
        A1[1] = ffma2(v.y, d1, A1[1]);
    }

    // nu=2: pairs of rows within each a-group (5 LDS / 2 rows)
    #pragma unroll
    for (int a = 0; a < 9; a++) {
        const int L = 9 - a;
        const char* go = sbc + OFFS.B[a];
        #pragma unroll
        for (int k = 0; k + 1 < L; k += 2) {
            const u64 P0 = fmul2(f2[a], f2[a + k]);
            const u64 P1 = fmul2(f2[a], f2[a + k + 1]);
            const u64 d00 = duplo(P0), d01 = duphi(P0);
            const u64 d10 = duplo(P1), d11 = duphi(P1);
            const char* base = go + (k / 2) * 80;
            const ulonglong2 x0 = *reinterpret_cast<const ulonglong2*>(base);
            const ulonglong2 x1 = *reinterpret_cast<const ulonglong2*>(base + 16);
            const ulonglong2 x2 = *reinterpret_cast<const ulonglong2*>(base + 32);
            const ulonglong2 x3 = *reinterpret_cast<const ulonglong2*>(base + 48);
            const ulonglong2 x4 = *reinterpret_cast<const ulonglong2*>(base + 64);
            acc5(B0, B1, x0.x, x0.y, x1.x, x1.y, x2.x, d00, d01);
            acc5(B0, B1, x2.y, x3.x, x3.y, x4.x, x4.y, d10, d11);
        }
        if (L & 1) {
            const int k = L - 1;
            const u64 P = fmul2(f2[a], f2[a + k]);
            const u64 d0 = duplo(P), d1 = duphi(P);
            const char* base = go + (k / 2) * 80;
            const ulonglong2 x0 = *reinterpret_cast<const ulonglong2*>(base);
            const ulonglong2 x1 = *reinterpret_cast<const ulonglong2*>(base + 16);
            const u64 x2 = *reinterpret_cast<const u64*>(base + 32);
            acc5(B0, B1, x0.x, x0.y, x1.x, x1.y, x2, d0, d1);
        }
    }

    // nu=3: pairs of rows within each (a,b) c-group (5 LDS / 2 rows, Pab shared)
    {
        int pr = 0;
        #pragma unroll
        for (int a = 0; a < 9; a++) {
            #pragma unroll
            for (int b = a; b < 9; b++) {
                const u64 Pab = fmul2(f2[a], f2[b]);
                const int L = 9 - b;
                const char* go = sbc + OFFS.C[pr];
                #pragma unroll
                for (int k = 0; k + 1 < L; k += 2) {
                    const u64 F0 = fmul2(Pab, f2[b + k]);
                    const u64 F1 = fmul2(Pab, f2[b + k + 1]);
                    const u64 d00 = duplo(F0), d01 = duphi(F0);
                    const u64 d10 = duplo(F1), d11 = duphi(F1);
                    const char* base = go + (k / 2) * 80;
                    const ulonglong2 x0 = *reinterpret_cast<const ulonglong2*>(base);
                    const ulonglong2 x1 = *reinterpret_cast<const ulonglong2*>(base + 16);
                    const ulonglong2 x2 = *reinterpret_cast<const ulonglong2*>(base + 32);
                    const ulonglong2 x3 = *reinterpret_cast<const ulonglong2*>(base + 48);
                    const ulonglong2 x4 = *reinterpret_cast<const ulonglong2*>(base + 64);
                    acc5(C0, C1, x0.x, x0.y, x1.x, x1.y, x2.x, d00, d01);
                    acc5(C0, C1, x2.y, x3.x, x3.y, x4.x, x4.y, d10, d11);
                }
                if (L & 1) {
                    const int k = L - 1;
                    const u64 F = fmul2(Pab, f2[b + k]);
                    const u64 d0 = duplo(F), d1 = duphi(F);
                    const char* base = go + (k / 2) * 80;
                    const ulonglong2 x0 = *reinterpret_cast<const ulonglong2*>(base);
                    const ulonglong2 x1 = *reinterpret_cast<const ulonglong2*>(base + 16);
                    const u64 x2 = *reinterpret_cast<const u64*>(base + 32);
                    acc5(C0, C1, x0.x, x0.y, x1.x, x1.y, x2, d0, d1);
                }
                pr++;
            }
        }
    }

    // unpack accumulators and run per-item epilogue
    float* obase = out + n * 512;
    {
        float TAs[4], TBs[10], TCs[10];
        upk2(TAs[0], TAs[1], A0[0]); upk2(TAs[2], TAs[3], A0[1]);
        #pragma unroll
        for (int q = 0; q < 5; q++) upk2(TBs[2 * q], TBs[2 * q + 1], B0[q]);
        #pragma unroll
        for (int q = 0; q < 5; q++) upk2(TCs[2 * q], TCs[2 * q + 1], C0[q]);
        epilogue(TAs, TBs, TCs, W0, W1, W2, W3, W4, W5, e, m0, obase);
    }
    {
        float TAs[4], TBs[10], TCs[10];
        upk2(TAs[0], TAs[1], A1[0]); upk2(TAs[2], TAs[3], A1[1]);
        #pragma unroll
        for (int q = 0; q < 5; q++) upk2(TBs[2 * q], TBs[2 * q + 1], B1[q]);
        #pragma unroll
        for (int q = 0; q < 5; q++) upk2(TCs[2 * q], TCs[2 * q + 1], C1[q]);
        epilogue(TAs, TBs, TCs, W0, W1, W2, W3, W4, W5, e, m1, obase);
    }
}

// ---------------------------------------------------------------------------
extern "C" void kernel_launch(void* const* d_in, const int* in_sizes, int n_in,
                              void* d_out, int out_size)
{
    const float* feats   = (const float*)d_in[0];
    const int*   species = (const int*)  d_in[1];
    const float* b0 = (const float*)d_in[2];
    const float* w0 = (const float*)d_in[3];
    const float* b1 = (const float*)d_in[4];
    const float* w1 = (const float*)d_in[5];
    const float* b2 = (const float*)d_in[6];
    const float* w2 = (const float*)d_in[7];
    const float* b3 = (const float*)d_in[8];
    const float* w3 = (const float*)d_in[9];
    const float* b4 = (const float*)d_in[10];
    const float* w4 = (const float*)d_in[11];
    const float* b5 = (const float*)d_in[12];
    const float* w5 = (const float*)d_in[13];
    float* out = (float*)d_out;

    dim3 block(64, 4);
    dim3 grid(2048 / 4);
    symcon_kernel<<<grid, block>>>(feats, species,
                                   b0, b1, b2, b3, b4, b5,
                                   w0, w1, w2, w3, w4, w5, out);
}